// round 2
// baseline (speedup 1.0000x reference)
#include <cuda_runtime.h>

#define cB   2
#define cT   2048
#define cHID 1024
#define cH   16
#define cHKV 16
#define cD   64
#define cNH  (cH + 2*cHKV)   // 48

// Scratch (device globals — no runtime allocation)
__device__ float g_qkv[(size_t)cB*cT*cNH*cD];   // (B,T,48,64)
__device__ float g_ctx[(size_t)cB*cT*cH*cD];    // (B,T,16,64)

// ---------------------------------------------------------------------------
// C[M,N] = A[M,K] @ B[N,K]^T   (both row-major, K contiguous)
// 64x64 tile, BK=32, 256 threads, 4x4 micro-tile.
// ---------------------------------------------------------------------------
__global__ __launch_bounds__(256) void gemm_tn(
    const float* __restrict__ A, const float* __restrict__ B,
    float* __restrict__ C, int M, int N, int K)
{
    __shared__ float sA[32][65];
    __shared__ float sB[32][65];
    int tid = threadIdx.x;
    int tx = tid & 15, ty = tid >> 4;
    int m0 = blockIdx.y << 6, n0 = blockIdx.x << 6;

    float acc[4][4] = {};
    for (int k0 = 0; k0 < K; k0 += 32) {
        #pragma unroll
        for (int i = 0; i < 2; i++) {
            int l = tid + (i << 8);           // 512 float4 per tile
            int row = l >> 3, kq = (l & 7) << 2;
            float4 va = *(const float4*)(A + (size_t)(m0 + row) * K + k0 + kq);
            sA[kq+0][row] = va.x; sA[kq+1][row] = va.y;
            sA[kq+2][row] = va.z; sA[kq+3][row] = va.w;
            float4 vb = *(const float4*)(B + (size_t)(n0 + row) * K + k0 + kq);
            sB[kq+0][row] = vb.x; sB[kq+1][row] = vb.y;
            sB[kq+2][row] = vb.z; sB[kq+3][row] = vb.w;
        }
        __syncthreads();
        #pragma unroll
        for (int kk = 0; kk < 32; kk++) {
            float a[4], b[4];
            #pragma unroll
            for (int i = 0; i < 4; i++) a[i] = sA[kk][ty*4+i];
            #pragma unroll
            for (int j = 0; j < 4; j++) b[j] = sB[kk][tx*4+j];
            #pragma unroll
            for (int i = 0; i < 4; i++)
                #pragma unroll
                for (int j = 0; j < 4; j++)
                    acc[i][j] = fmaf(a[i], b[j], acc[i][j]);
        }
        __syncthreads();
    }
    #pragma unroll
    for (int i = 0; i < 4; i++) {
        float4 v = make_float4(acc[i][0], acc[i][1], acc[i][2], acc[i][3]);
        *(float4*)(C + (size_t)(m0 + ty*4 + i) * N + n0 + tx*4) = v;
    }
}

// ---------------------------------------------------------------------------
// In-place RoPE on Q and K heads. One thread per (b,t,h,d<32) pair.
// cos/sin tables: emb = concat(freqs,freqs) -> cos[t,d] == cos[t,d+32].
// ---------------------------------------------------------------------------
__global__ __launch_bounds__(256) void rope_kernel(
    float* __restrict__ qkv,
    const float* __restrict__ cosT, const float* __restrict__ sinT)
{
    int idx = blockIdx.x * 256 + threadIdx.x;   // exactly B*T*32*32 threads
    int d  = idx & 31;
    int h  = (idx >> 5) & 31;                   // 0..31  (H+HKV = 32 heads)
    int bt = idx >> 10;                         // 0..B*T-1
    int t  = bt & (cT - 1);
    float c = cosT[t*cD + d];
    float s = sinT[t*cD + d];
    float* p = qkv + ((size_t)bt * cNH + h) * cD;
    float x1 = p[d], x2 = p[d + 32];
    p[d]      = x1 * c - x2 * s;
    p[d + 32] = x2 * c + x1 * s;
}

// ---------------------------------------------------------------------------
// Flash attention (causal). Block = (b, h, 64-row Q tile). 256 threads.
// 64x64 S tile, 4x4 micro, online softmax, P reuses the K smem buffer.
// sQ/sK/P use XOR-32 swizzle for conflict-free column reads; sV is plain.
// ---------------------------------------------------------------------------
__device__ __forceinline__ int sw(int r, int c) { return c ^ (r & 31); }

__global__ __launch_bounds__(256) void attn_kernel(
    const float* __restrict__ qkv, float* __restrict__ ctx)
{
    __shared__ float sQ [64][64];
    __shared__ float sKP[64][64];   // K tile, then reused for P
    __shared__ float sV [64][64];

    int tid = threadIdx.x;
    int tx = tid & 15, ty = tid >> 4;
    int qt = blockIdx.x, h = blockIdx.y, b = blockIdx.z;
    int q0 = qt << 6;

    // Load Q tile (swizzled)
    #pragma unroll
    for (int i = 0; i < 4; i++) {
        int l = tid + (i << 8);
        int row = l >> 4, c4 = (l & 15) << 2;
        float4 v = *(const float4*)(qkv + ((size_t)(b*cT + q0 + row) * cNH + h) * cD + c4);
        sQ[row][sw(row, c4+0)] = v.x;
        sQ[row][sw(row, c4+1)] = v.y;
        sQ[row][sw(row, c4+2)] = v.z;
        sQ[row][sw(row, c4+3)] = v.w;
    }

    float o[4][4] = {};
    float m_r[4], l_r[4];
    #pragma unroll
    for (int i = 0; i < 4; i++) { m_r[i] = -1e30f; l_r[i] = 0.f; }

    const float scale = 0.125f;   // 1/sqrt(64)

    for (int kt = 0; kt <= qt; kt++) {
        int k0 = kt << 6;
        __syncthreads();   // protect sKP/sV from previous iteration readers

        // Load K (swizzled) and V (plain) tiles
        #pragma unroll
        for (int i = 0; i < 4; i++) {
            int l = tid + (i << 8);
            int row = l >> 4, c4 = (l & 15) << 2;
            size_t base = (size_t)(b*cT + k0 + row) * cNH;
            float4 kv = *(const float4*)(qkv + (base + cH       + h) * cD + c4);
            sKP[row][sw(row, c4+0)] = kv.x; sKP[row][sw(row, c4+1)] = kv.y;
            sKP[row][sw(row, c4+2)] = kv.z; sKP[row][sw(row, c4+3)] = kv.w;
            float4 vv = *(const float4*)(qkv + (base + cH + cHKV + h) * cD + c4);
            sV[row][c4+0] = vv.x; sV[row][c4+1] = vv.y;
            sV[row][c4+2] = vv.z; sV[row][c4+3] = vv.w;
        }
        __syncthreads();

        // S = Q @ K^T
        float s[4][4] = {};
        #pragma unroll
        for (int kk = 0; kk < 64; kk++) {
            float a[4], bb[4];
            #pragma unroll
            for (int i = 0; i < 4; i++) a[i]  = sQ [ty*4+i][sw(ty*4+i, kk)];
            #pragma unroll
            for (int j = 0; j < 4; j++) bb[j] = sKP[tx*4+j][sw(tx*4+j, kk)];
            #pragma unroll
            for (int i = 0; i < 4; i++)
                #pragma unroll
                for (int j = 0; j < 4; j++)
                    s[i][j] = fmaf(a[i], bb[j], s[i][j]);
        }

        // Scale + causal mask (only the diagonal tile needs element masking)
        bool diag = (kt == qt);
        #pragma unroll
        for (int i = 0; i < 4; i++)
            #pragma unroll
            for (int j = 0; j < 4; j++) {
                s[i][j] *= scale;
                if (diag && (tx*4 + j > ty*4 + i)) s[i][j] = -1e30f;
            }

        // Online softmax (row reductions over the 16 tx-lanes via shuffle)
        #pragma unroll
        for (int i = 0; i < 4; i++) {
            float mx = fmaxf(fmaxf(s[i][0], s[i][1]), fmaxf(s[i][2], s[i][3]));
            #pragma unroll
            for (int off = 8; off >= 1; off >>= 1)
                mx = fmaxf(mx, __shfl_xor_sync(0xffffffffu, mx, off));
            float mnew = fmaxf(m_r[i], mx);
            float corr = __expf(m_r[i] - mnew);
            m_r[i] = mnew;
            float rs = 0.f;
            #pragma unroll
            for (int j = 0; j < 4; j++) { s[i][j] = __expf(s[i][j] - mnew); rs += s[i][j]; }
            #pragma unroll
            for (int off = 8; off >= 1; off >>= 1)
                rs += __shfl_xor_sync(0xffffffffu, rs, off);
            l_r[i] = l_r[i] * corr + rs;
            #pragma unroll
            for (int j = 0; j < 4; j++) o[i][j] *= corr;
        }

        // Stage P into smem (reuse sKP), then O += P @ V
        __syncthreads();
        #pragma unroll
        for (int i = 0; i < 4; i++)
            #pragma unroll
            for (int j = 0; j < 4; j++)
                sKP[ty*4+i][sw(ty*4+i, tx*4+j)] = s[i][j];
        __syncthreads();

        #pragma unroll
        for (int kk = 0; kk < 64; kk++) {
            float p[4], v[4];
            #pragma unroll
            for (int i = 0; i < 4; i++) p[i] = sKP[ty*4+i][sw(ty*4+i, kk)];
            #pragma unroll
            for (int j = 0; j < 4; j++) v[j] = sV[kk][tx*4+j];
            #pragma unroll
            for (int i = 0; i < 4; i++)
                #pragma unroll
                for (int j = 0; j < 4; j++)
                    o[i][j] = fmaf(p[i], v[j], o[i][j]);
        }
    }

    // Normalize and store context: (B, T, H, D) == (B*T, 1024)
    #pragma unroll
    for (int i = 0; i < 4; i++) {
        float inv = 1.0f / l_r[i];
        float4 v = make_float4(o[i][0]*inv, o[i][1]*inv, o[i][2]*inv, o[i][3]*inv);
        *(float4*)(ctx + ((size_t)(b*cT + q0 + ty*4 + i) * cH + h) * cD + tx*4) = v;
    }
}

// ---------------------------------------------------------------------------
extern "C" void kernel_launch(void* const* d_in, const int* in_sizes, int n_in,
                              void* d_out, int out_size)
{
    const float* hidden = (const float*)d_in[0];   // (B,T,1024)
    const float* cosT   = (const float*)d_in[1];   // (T,64)
    const float* sinT   = (const float*)d_in[2];   // (T,64)
    const float* w_qkv  = (const float*)d_in[3];   // (3072,1024)
    const float* w_o    = (const float*)d_in[4];   // (1024,1024)
    float* out = (float*)d_out;                    // (B,T,1024)

    float *qkv, *ctx;
    cudaGetSymbolAddress((void**)&qkv, g_qkv);
    cudaGetSymbolAddress((void**)&ctx, g_ctx);

    const int M = cB * cT;                         // 4096

    // 1) QKV projection: (4096,1024) @ (3072,1024)^T
    gemm_tn<<<dim3((cNH*cD)/64, M/64), 256>>>(hidden, w_qkv, qkv, M, cNH*cD, cHID);

    // 2) RoPE on Q and K heads (in place)
    rope_kernel<<<(cB*cT*(cH+cHKV)*(cD/2))/256, 256>>>(qkv, cosT, sinT);

    // 3) Causal flash attention
    attn_kernel<<<dim3(cT/64, cH, cB), 256>>>(qkv, ctx);

    // 4) Output projection: (4096,1024) @ (1024,1024)^T
    gemm_tn<<<dim3(cHID/64, M/64), 256>>>(ctx, w_o, out, M, cHID, cHID);
}

// round 3
// speedup vs baseline: 1.5223x; 1.5223x over previous
#include <cuda_runtime.h>

#define cB   2
#define cT   2048
#define cHID 1024
#define cH   16
#define cHKV 16
#define cD   64
#define cNH  (cH + 2*cHKV)   // 48

// Scratch (device globals — no runtime allocation)
__device__ float g_qkv[(size_t)cB*cT*cNH*cD];   // (B,T,48,64)
__device__ float g_ctx[(size_t)cB*cT*cH*cD];    // (B,T,16,64)

// ---------------------------------------------------------------------------
// C[M,N] = A[M,K] @ B[N,K]^T  (row-major, K contiguous).
// 128x128 tile, BK=16, 256 threads, 8x8 micro (frags split at +64).
// Double-buffered smem, register prefetch, 1 sync per k-block.
// ---------------------------------------------------------------------------
__global__ __launch_bounds__(256, 2) void gemm_tn(
    const float* __restrict__ A, const float* __restrict__ B,
    float* __restrict__ C, int M, int N, int K)
{
    __shared__ float sA[2][16][128];
    __shared__ float sB[2][16][128];

    int tid = threadIdx.x;
    int tx = tid & 15, ty = tid >> 4;
    int m0 = blockIdx.y << 7, n0 = blockIdx.x << 7;

    int lrow = tid & 127;          // 0..127
    int lk   = (tid >> 7) << 3;    // 0 or 8

    const float* Ap = A + (size_t)(m0 + lrow) * K + lk;
    const float* Bp = B + (size_t)(n0 + lrow) * K + lk;

    float4 ra0 = *(const float4*)(Ap + 0);
    float4 ra1 = *(const float4*)(Ap + 4);
    float4 rb0 = *(const float4*)(Bp + 0);
    float4 rb1 = *(const float4*)(Bp + 4);

    sA[0][lk+0][lrow]=ra0.x; sA[0][lk+1][lrow]=ra0.y; sA[0][lk+2][lrow]=ra0.z; sA[0][lk+3][lrow]=ra0.w;
    sA[0][lk+4][lrow]=ra1.x; sA[0][lk+5][lrow]=ra1.y; sA[0][lk+6][lrow]=ra1.z; sA[0][lk+7][lrow]=ra1.w;
    sB[0][lk+0][lrow]=rb0.x; sB[0][lk+1][lrow]=rb0.y; sB[0][lk+2][lrow]=rb0.z; sB[0][lk+3][lrow]=rb0.w;
    sB[0][lk+4][lrow]=rb1.x; sB[0][lk+5][lrow]=rb1.y; sB[0][lk+6][lrow]=rb1.z; sB[0][lk+7][lrow]=rb1.w;
    __syncthreads();

    float acc[8][8] = {};
    const int NK = K >> 4;
    int buf = 0;

    for (int kb = 0; kb < NK; ++kb) {
        if (kb + 1 < NK) {
            const float* An = Ap + (kb + 1) * 16;
            const float* Bn = Bp + (kb + 1) * 16;
            ra0 = *(const float4*)(An + 0);
            ra1 = *(const float4*)(An + 4);
            rb0 = *(const float4*)(Bn + 0);
            rb1 = *(const float4*)(Bn + 4);
        }
        #pragma unroll
        for (int kk = 0; kk < 16; ++kk) {
            float a[8], b[8];
            *(float4*)&a[0] = *(const float4*)&sA[buf][kk][ty*4];
            *(float4*)&a[4] = *(const float4*)&sA[buf][kk][64 + ty*4];
            *(float4*)&b[0] = *(const float4*)&sB[buf][kk][tx*4];
            *(float4*)&b[4] = *(const float4*)&sB[buf][kk][64 + tx*4];
            #pragma unroll
            for (int i = 0; i < 8; ++i)
                #pragma unroll
                for (int j = 0; j < 8; ++j)
                    acc[i][j] = fmaf(a[i], b[j], acc[i][j]);
        }
        if (kb + 1 < NK) {
            int nb = buf ^ 1;
            sA[nb][lk+0][lrow]=ra0.x; sA[nb][lk+1][lrow]=ra0.y; sA[nb][lk+2][lrow]=ra0.z; sA[nb][lk+3][lrow]=ra0.w;
            sA[nb][lk+4][lrow]=ra1.x; sA[nb][lk+5][lrow]=ra1.y; sA[nb][lk+6][lrow]=ra1.z; sA[nb][lk+7][lrow]=ra1.w;
            sB[nb][lk+0][lrow]=rb0.x; sB[nb][lk+1][lrow]=rb0.y; sB[nb][lk+2][lrow]=rb0.z; sB[nb][lk+3][lrow]=rb0.w;
            sB[nb][lk+4][lrow]=rb1.x; sB[nb][lk+5][lrow]=rb1.y; sB[nb][lk+6][lrow]=rb1.z; sB[nb][lk+7][lrow]=rb1.w;
            __syncthreads();
            buf = nb;
        }
    }

    #pragma unroll
    for (int i = 0; i < 8; ++i) {
        int row = m0 + ((i < 4) ? (ty*4 + i) : (64 + ty*4 + i - 4));
        float* Cr = C + (size_t)row * N + n0;
        *(float4*)(Cr + tx*4)      = make_float4(acc[i][0], acc[i][1], acc[i][2], acc[i][3]);
        *(float4*)(Cr + 64 + tx*4) = make_float4(acc[i][4], acc[i][5], acc[i][6], acc[i][7]);
    }
}

// ---------------------------------------------------------------------------
// In-place RoPE on Q and K heads. One thread per (b,t,h,d<32) pair.
// ---------------------------------------------------------------------------
__global__ __launch_bounds__(256) void rope_kernel(
    float* __restrict__ qkv,
    const float* __restrict__ cosT, const float* __restrict__ sinT)
{
    int idx = blockIdx.x * 256 + threadIdx.x;
    int d  = idx & 31;
    int h  = (idx >> 5) & 31;        // heads 0..31 (Q + K)
    int bt = idx >> 10;
    int t  = bt & (cT - 1);
    float c = cosT[t*cD + d];
    float s = sinT[t*cD + d];
    float* p = qkv + ((size_t)bt * cNH + h) * cD;
    float x1 = p[d], x2 = p[d + 32];
    p[d]      = x1 * c - x2 * s;
    p[d + 32] = x2 * c + x1 * s;
}

// ---------------------------------------------------------------------------
// Flash attention (causal). Block = (b, h, 128-row Q tile). 256 threads.
// S tile 128x64, micro 8x4. Q/K/P stored transposed in smem so mainloop
// operand reads are all LDS.128. Dynamic smem ~101KB -> 2 CTAs/SM.
// ---------------------------------------------------------------------------
#define QSTR 132   // sQ/sP row stride ([d or key][row..128])
#define KSTR 68    // sK/sV stride

__global__ __launch_bounds__(256, 2) void attn_kernel(
    const float* __restrict__ qkv, float* __restrict__ ctx)
{
    extern __shared__ float sm[];
    float* sQ = sm;                       // [64][QSTR]  (d, qrow)
    float* sK = sQ + 64*QSTR;             // [64][KSTR]  (d, key)
    float* sV = sK + 64*KSTR;             // [64][KSTR]  (key, d)
    float* sP = sV + 64*KSTR;             // [64][QSTR]  (key, qrow)

    int tid = threadIdx.x;
    int tx = tid & 15, ty = tid >> 4;
    int qt = gridDim.x - 1 - blockIdx.x;   // heavy tiles first
    int h = blockIdx.y, b = blockIdx.z;
    int q0 = qt << 7;

    // Load Q tile, transposed: sQ[d][row]
    #pragma unroll
    for (int i = 0; i < 8; ++i) {
        int idx = tid + (i << 8);
        int row = idx >> 4, d4 = (idx & 15) << 2;
        float4 v = *(const float4*)(qkv + ((size_t)(b*cT + q0 + row) * cNH + h) * cD + d4);
        sQ[(d4+0)*QSTR + row] = v.x;
        sQ[(d4+1)*QSTR + row] = v.y;
        sQ[(d4+2)*QSTR + row] = v.z;
        sQ[(d4+3)*QSTR + row] = v.w;
    }

    float o[8][4] = {};
    float m_r[8], l_r[8];
    #pragma unroll
    for (int i = 0; i < 8; ++i) { m_r[i] = -1e30f; l_r[i] = 0.f; }

    const float scale = 0.125f;  // 1/sqrt(64)
    int r_loc[8];
    #pragma unroll
    for (int i = 0; i < 8; ++i) r_loc[i] = (i < 4) ? (ty*4 + i) : (64 + ty*4 + i - 4);

    const int ktmax = 2*qt + 1;
    for (int kt = 0; kt <= ktmax; ++kt) {
        int k0 = kt << 6;
        __syncthreads();   // protect sK/sV/sP from previous-iteration readers

        // Load K (transposed) and V (natural) tiles
        #pragma unroll
        for (int i = 0; i < 4; ++i) {
            int idx = tid + (i << 8);
            int key = idx >> 4, d4 = (idx & 15) << 2;
            size_t base = (size_t)(b*cT + k0 + key) * cNH;
            float4 kv = *(const float4*)(qkv + (base + cH + h) * cD + d4);
            sK[(d4+0)*KSTR + key] = kv.x;
            sK[(d4+1)*KSTR + key] = kv.y;
            sK[(d4+2)*KSTR + key] = kv.z;
            sK[(d4+3)*KSTR + key] = kv.w;
            float4 vv = *(const float4*)(qkv + (base + cH + cHKV + h) * cD + d4);
            *(float4*)&sV[key*KSTR + d4] = vv;
        }
        __syncthreads();

        // S = Q @ K^T   (128x64, kk over D=64)
        float s[8][4] = {};
        #pragma unroll
        for (int kk = 0; kk < 64; ++kk) {
            float a[8], bb[4];
            *(float4*)&a[0]  = *(const float4*)&sQ[kk*QSTR + ty*4];
            *(float4*)&a[4]  = *(const float4*)&sQ[kk*QSTR + 64 + ty*4];
            *(float4*)&bb[0] = *(const float4*)&sK[kk*KSTR + tx*4];
            #pragma unroll
            for (int i = 0; i < 8; ++i)
                #pragma unroll
                for (int j = 0; j < 4; ++j)
                    s[i][j] = fmaf(a[i], bb[j], s[i][j]);
        }

        // Scale + causal mask (only last two kt tiles cross the diagonal)
        bool need_mask = (kt >= 2*qt);
        #pragma unroll
        for (int i = 0; i < 8; ++i)
            #pragma unroll
            for (int j = 0; j < 4; ++j) {
                s[i][j] *= scale;
                if (need_mask && (k0 + tx*4 + j > q0 + r_loc[i])) s[i][j] = -1e30f;
            }

        // Online softmax: row reductions over the 16 tx lanes
        #pragma unroll
        for (int i = 0; i < 8; ++i) {
            float mx = fmaxf(fmaxf(s[i][0], s[i][1]), fmaxf(s[i][2], s[i][3]));
            #pragma unroll
            for (int off = 8; off >= 1; off >>= 1)
                mx = fmaxf(mx, __shfl_xor_sync(0xffffffffu, mx, off));
            float mnew = fmaxf(m_r[i], mx);
            float corr = __expf(m_r[i] - mnew);
            m_r[i] = mnew;
            float rs = 0.f;
            #pragma unroll
            for (int j = 0; j < 4; ++j) { s[i][j] = __expf(s[i][j] - mnew); rs += s[i][j]; }
            #pragma unroll
            for (int off = 8; off >= 1; off >>= 1)
                rs += __shfl_xor_sync(0xffffffffu, rs, off);
            l_r[i] = l_r[i] * corr + rs;
            #pragma unroll
            for (int j = 0; j < 4; ++j) o[i][j] *= corr;
        }

        // Stage P transposed: sP[key][row]
        #pragma unroll
        for (int i = 0; i < 8; ++i)
            #pragma unroll
            for (int j = 0; j < 4; ++j)
                sP[(tx*4 + j)*QSTR + r_loc[i]] = s[i][j];
        __syncthreads();

        // O += P @ V  (kk over 64 keys)
        #pragma unroll
        for (int kk = 0; kk < 64; ++kk) {
            float p[8], v[4];
            *(float4*)&p[0] = *(const float4*)&sP[kk*QSTR + ty*4];
            *(float4*)&p[4] = *(const float4*)&sP[kk*QSTR + 64 + ty*4];
            *(float4*)&v[0] = *(const float4*)&sV[kk*KSTR + tx*4];
            #pragma unroll
            for (int i = 0; i < 8; ++i)
                #pragma unroll
                for (int j = 0; j < 4; ++j)
                    o[i][j] = fmaf(p[i], v[j], o[i][j]);
        }
    }

    // Normalize + store context (B,T,H,D)
    #pragma unroll
    for (int i = 0; i < 8; ++i) {
        float inv = 1.0f / l_r[i];
        float4 v = make_float4(o[i][0]*inv, o[i][1]*inv, o[i][2]*inv, o[i][3]*inv);
        *(float4*)(ctx + ((size_t)(b*cT + q0 + r_loc[i]) * cH + h) * cD + tx*4) = v;
    }
}

// ---------------------------------------------------------------------------
extern "C" void kernel_launch(void* const* d_in, const int* in_sizes, int n_in,
                              void* d_out, int out_size)
{
    const float* hidden = (const float*)d_in[0];   // (B,T,1024)
    const float* cosT   = (const float*)d_in[1];   // (T,64)
    const float* sinT   = (const float*)d_in[2];   // (T,64)
    const float* w_qkv  = (const float*)d_in[3];   // (3072,1024)
    const float* w_o    = (const float*)d_in[4];   // (1024,1024)
    float* out = (float*)d_out;                    // (B,T,1024)

    float *qkv, *ctx;
    cudaGetSymbolAddress((void**)&qkv, g_qkv);
    cudaGetSymbolAddress((void**)&ctx, g_ctx);

    const int M = cB * cT;                         // 4096
    const int attn_smem = (64*QSTR + 64*KSTR + 64*KSTR + 64*QSTR) * (int)sizeof(float);
    cudaFuncSetAttribute(attn_kernel, cudaFuncAttributeMaxDynamicSharedMemorySize, attn_smem);

    // 1) QKV projection: (4096,1024) @ (3072,1024)^T
    gemm_tn<<<dim3((cNH*cD)/128, M/128), 256>>>(hidden, w_qkv, qkv, M, cNH*cD, cHID);

    // 2) RoPE on Q and K heads (in place)
    rope_kernel<<<(cB*cT*(cH+cHKV)*(cD/2))/256, 256>>>(qkv, cosT, sinT);

    // 3) Causal flash attention
    attn_kernel<<<dim3(cT/128, cH, cB), 256, attn_smem>>>(qkv, ctx);

    // 4) Output projection: (4096,1024) @ (1024,1024)^T
    gemm_tn<<<dim3(cHID/128, M/128), 256>>>(ctx, w_o, out, M, cHID, cHID);
}